// round 1
// baseline (speedup 1.0000x reference)
#include <cuda_runtime.h>
#include <cstdint>

// ---------------------------------------------------------------------------
// Sinkhorn-Knopp on 65536 independent 32x32 matrices.
//
// Exploits: M after any number of row/col normalizations equals
//   diag(u) * M0 * diag(v)
// since each normalization step  M <- M / (sum + eps)  is a diagonal rescale.
// So we keep M0 fixed (registers) and iterate only on the 32-vectors u, v:
//   d_i = sum_j M0[i][j] v_j ;  u_i <- u_i / (u_i d_i + eps)
//   c_j = sum_i M0[i][j] u_i ;  v_j <- v_j / (v_j c_j + eps)
//
// One warp per matrix. Lane l holds row l (Mr) and column l (Mc) of M0,
// each packed into 16 f32x2 (.b64) registers, so both matvec directions are
// in-lane dot products using fma.rn.f32x2 (2x fp32 fma rate on sm_103a).
// u/v broadcast across lanes goes through shared memory with LDS.128
// broadcast reads (8 per matvec).
// ---------------------------------------------------------------------------

#define FMA2(d, a, b, c) \
    asm("fma.rn.f32x2 %0, %1, %2, %3;" : "=l"(d) : "l"(a), "l"(b), "l"(c))
#define MUL2(d, a, b) \
    asm("mul.rn.f32x2 %0, %1, %2;" : "=l"(d) : "l"(a), "l"(b))
#define ADD2(d, a, b) \
    asm("add.rn.f32x2 %0, %1, %2;" : "=l"(d) : "l"(a), "l"(b))
#define PACK2(d, lo, hi) \
    asm("mov.b64 %0, {%1, %2};" : "=l"(d) : "f"(lo), "f"(hi))
#define UNPACK2(lo, hi, s) \
    asm("mov.b64 {%0, %1}, %2;" : "=f"(lo), "=f"(hi) : "l"(s))

static constexpr float EPS      = 1e-8f;
static constexpr float INV_TAU  = 10.0f;   // 1 / 0.1
static constexpr int   WPB      = 8;       // warps (matrices) per block
static constexpr int   SROW     = 36;      // smem row stride (floats): 144B,
                                           // 16B aligned, conflict-free both ways

__global__ __launch_bounds__(WPB * 32, 2)
void sinkhorn_kernel(const float* __restrict__ H,
                     float* __restrict__ Out,
                     int nmat) {
    // Per-warp scratch: 32x32 tile with padded stride + u/v vectors.
    __shared__ __align__(16) float S[WPB][32 * SROW];
    __shared__ __align__(16) float Ubuf[WPB][32];
    __shared__ __align__(16) float Vbuf[WPB][32];

    const int w    = threadIdx.x >> 5;
    const int lane = threadIdx.x & 31;
    const int m    = blockIdx.x * WPB + w;
    if (m >= nmat) return;   // whole warp exits together

    float* s   = S[w];
    float* usm = Ubuf[w];
    float* vsm = Vbuf[w];

    const float4* src = reinterpret_cast<const float4*>(H)   + (size_t)m * 256;
    float4*       dst = reinterpret_cast<float4*>(Out)       + (size_t)m * 256;

    // ---- Load (fully coalesced), exp/clamp, scatter into padded smem tile ----
#pragma unroll
    for (int k = 0; k < 8; k++) {
        float4 q = src[k * 32 + lane];            // 512B contiguous per warp-inst
        q.x = fmaxf(__expf(q.x * INV_TAU), EPS);
        q.y = fmaxf(__expf(q.y * INV_TAU), EPS);
        q.z = fmaxf(__expf(q.z * INV_TAU), EPS);
        q.w = fmaxf(__expf(q.w * INV_TAU), EPS);
        const int e = k * 128 + lane * 4;         // flat element index
        const int r = e >> 5;                     // row
        const int c = e & 31;                     // col (multiple of 4)
        *reinterpret_cast<float4*>(s + r * SROW + c) = q;   // conflict-free STS.128
    }
    vsm[lane] = 1.0f;
    __syncwarp();

    // ---- Pull row l and column l into packed f32x2 registers ----
    unsigned long long Mr[16];   // row  l: pairs (col 2t, col 2t+1)
    unsigned long long Mc[16];   // col  l: pairs (row 2t, row 2t+1)
    {
        const ulonglong2* rp = reinterpret_cast<const ulonglong2*>(s + lane * SROW);
#pragma unroll
        for (int t = 0; t < 8; t++) {             // conflict-free LDS.128
            ulonglong2 q = rp[t];
            Mr[2 * t]     = q.x;
            Mr[2 * t + 1] = q.y;
        }
#pragma unroll
        for (int t = 0; t < 16; t++) {            // conflict-free scalar column reads
            float a = s[(2 * t)     * SROW + lane];
            float b = s[(2 * t + 1) * SROW + lane];
            PACK2(Mc[t], a, b);
        }
    }

    float u = 1.0f, v = 1.0f;

#pragma unroll 1
    for (int it = 0; it < 10; it++) {
        // ---- Row step: d_l = Mr . v ----
        {
            const ulonglong2* vp = reinterpret_cast<const ulonglong2*>(vsm);
            unsigned long long a0 = 0ull, a1 = 0ull;
#pragma unroll
            for (int t = 0; t < 8; t++) {
                ulonglong2 q = vp[t];             // LDS.128 broadcast
                FMA2(a0, Mr[2 * t],     q.x, a0);
                FMA2(a1, Mr[2 * t + 1], q.y, a1);
            }
            unsigned long long as;
            ADD2(as, a0, a1);
            float dlo, dhi;
            UNPACK2(dlo, dhi, as);
            const float d = dlo + dhi;
            u = __fdividef(u, fmaf(u, d, EPS));
            usm[lane] = u;
        }
        __syncwarp();

        // ---- Col step: c_l = Mc . u ----
        {
            const ulonglong2* up = reinterpret_cast<const ulonglong2*>(usm);
            unsigned long long a0 = 0ull, a1 = 0ull;
#pragma unroll
            for (int t = 0; t < 8; t++) {
                ulonglong2 q = up[t];
                FMA2(a0, Mc[2 * t],     q.x, a0);
                FMA2(a1, Mc[2 * t + 1], q.y, a1);
            }
            unsigned long long as;
            ADD2(as, a0, a1);
            float clo, chi;
            UNPACK2(clo, chi, as);
            const float cs = clo + chi;
            v = __fdividef(v, fmaf(v, cs, EPS));
            vsm[lane] = v;
        }
        __syncwarp();
    }

    // ---- Epilogue: out[l][j] = u_l * M0[l][j] * v_j ----
    {
        unsigned long long uu;
        PACK2(uu, u, u);
        const ulonglong2* vp = reinterpret_cast<const ulonglong2*>(vsm);
#pragma unroll
        for (int t = 0; t < 8; t++) {
            ulonglong2 q = vp[t];
            unsigned long long r0, r1;
            MUL2(r0, Mr[2 * t],     q.x);
            MUL2(r0, r0, uu);
            MUL2(r1, Mr[2 * t + 1], q.y);
            MUL2(r1, r1, uu);
            float4 o;
            UNPACK2(o.x, o.y, r0);
            UNPACK2(o.z, o.w, r1);
            dst[lane * 8 + t] = o;                // row l written as 8x STG.128
        }
    }
}

extern "C" void kernel_launch(void* const* d_in, const int* in_sizes, int n_in,
                              void* d_out, int out_size) {
    const float* H  = (const float*)d_in[0];
    float*       out = (float*)d_out;
    const int nmat  = in_sizes[0] / 1024;         // 32*32 elements per matrix
    const int blocks = (nmat + WPB - 1) / WPB;
    sinkhorn_kernel<<<blocks, WPB * 32>>>(H, out, nmat);
}

// round 2
// speedup vs baseline: 1.4793x; 1.4793x over previous
#include <cuda_runtime.h>
#include <cstdint>

// ---------------------------------------------------------------------------
// Sinkhorn-Knopp, 65536 independent 32x32 fp32 matrices, 10 iterations.
//
// M after any sequence of row/col normalizations is diag(u) * M0 * diag(v),
// so only the 32-vectors u, v are iterated:
//   d_i = sum_j M0[i][j] v_j ;  u_i <- u_i / (u_i d_i + eps)
//   c_j = sum_i M0[i][j] u_i ;  v_j <- v_j / (v_j c_j + eps)
//
// One warp per matrix, lanes arranged as an 8x4 grid: lane L -> (a=L>>2,
// b=L&3) owns the 4x8 subtile rows [4a,4a+4) x cols [8b,8b+8), held as 16
// f32x2 registers. u[i] lives on lane i; v[8b+c] lives on lane 4c+b.
// Per iteration each lane gathers only 12 scalars via SHFL.IDX and the
// matvec partials are combined with routed SHFL.XOR butterflies (f32x2
// payloads) — zero shared memory, zero barriers. This removes the L1
// crossbar broadcast wall (86.5% L1 in R1).
// ---------------------------------------------------------------------------

#define FMA2(d, a, b, c) \
    asm("fma.rn.f32x2 %0, %1, %2, %3;" : "=l"(d) : "l"(a), "l"(b), "l"(c))
#define MUL2(d, a, b) \
    asm("mul.rn.f32x2 %0, %1, %2;" : "=l"(d) : "l"(a), "l"(b))
#define ADD2(d, a, b) \
    asm("add.rn.f32x2 %0, %1, %2;" : "=l"(d) : "l"(a), "l"(b))
#define PACK2(d, lo, hi) \
    asm("mov.b64 %0, {%1, %2};" : "=l"(d) : "f"(lo), "f"(hi))
#define UNPACK2(lo, hi, s) \
    asm("mov.b64 {%0, %1}, %2;" : "=f"(lo), "=f"(hi) : "l"(s))

using ull = unsigned long long;

static constexpr float EPS     = 1e-8f;
static constexpr float INV_TAU = 10.0f;   // 1 / 0.1
static constexpr int   WPB     = 4;       // warps (matrices) per block
static constexpr unsigned FULL = 0xFFFFFFFFu;

__global__ __launch_bounds__(WPB * 32, 6)
void sinkhorn_kernel(const float* __restrict__ H,
                     float* __restrict__ Out,
                     int nmat) {
    const int lane = threadIdx.x & 31;
    const int w    = threadIdx.x >> 5;
    const int m    = blockIdx.x * WPB + w;
    if (m >= nmat) return;   // warp-uniform

    const int a = lane >> 2;     // 0..7  (row group: rows 4a..4a+3)
    const int b = lane & 3;      // 0..3  (col group: cols 8b..8b+7)

    const int hi_b = (b >> 1) & 1;   // b bit1
    const int lo_b = b & 1;          // b bit0
    const int h2   = (a >> 2) & 1;   // a bit2
    const int h1   = (a >> 1) & 1;   // a bit1
    const int h0   = a & 1;          // a bit0
    const int a4   = lane & ~3;      // 4a

    const float4* src = reinterpret_cast<const float4*>(H)  + (size_t)m * 256;
    float4*       dst = reinterpret_cast<float4*>(Out)      + (size_t)m * 256;

    // ---- Load subtile, exp/clamp, pack into f32x2 registers ----
    // M[r][s] = ( M0[4a+r][8b+2s], M0[4a+r][8b+2s+1] )
    ull M[4][4];
#pragma unroll
    for (int r = 0; r < 4; r++) {
        const int rowoff = (4 * a + r) * 8 + 2 * b;   // float4 index
#pragma unroll
        for (int q = 0; q < 2; q++) {
            float4 t = src[rowoff + q];
            t.x = fmaxf(__expf(t.x * INV_TAU), EPS);
            t.y = fmaxf(__expf(t.y * INV_TAU), EPS);
            t.z = fmaxf(__expf(t.z * INV_TAU), EPS);
            t.w = fmaxf(__expf(t.w * INV_TAU), EPS);
            PACK2(M[r][2 * q],     t.x, t.y);
            PACK2(M[r][2 * q + 1], t.z, t.w);
        }
    }

    float u = 1.0f, v = 1.0f;

#pragma unroll 1
    for (int it = 0; it < 10; it++) {
        // ================= Row step: d_i = M0[i,:].v, update u ==============
        {
            // gather v[8b+c], c=0..7 ; owner of v[8b+c] is lane 4c+b
            float g0 = __shfl_sync(FULL, v, b);
            float g1 = __shfl_sync(FULL, v, b + 4);
            float g2 = __shfl_sync(FULL, v, b + 8);
            float g3 = __shfl_sync(FULL, v, b + 12);
            float g4 = __shfl_sync(FULL, v, b + 16);
            float g5 = __shfl_sync(FULL, v, b + 20);
            float g6 = __shfl_sync(FULL, v, b + 24);
            float g7 = __shfl_sync(FULL, v, b + 28);
            ull V0, V1, V2, V3;
            PACK2(V0, g0, g1); PACK2(V1, g2, g3);
            PACK2(V2, g4, g5); PACK2(V3, g6, g7);

            // per-row partial dot over our 8 columns (f32x2 even/odd partials)
            ull A0, A1, A2, A3;
            MUL2(A0, M[0][0], V0); FMA2(A0, M[0][1], V1, A0);
            FMA2(A0, M[0][2], V2, A0); FMA2(A0, M[0][3], V3, A0);
            MUL2(A1, M[1][0], V0); FMA2(A1, M[1][1], V1, A1);
            FMA2(A1, M[1][2], V2, A1); FMA2(A1, M[1][3], V3, A1);
            MUL2(A2, M[2][0], V0); FMA2(A2, M[2][1], V1, A2);
            FMA2(A2, M[2][2], V2, A2); FMA2(A2, M[2][3], V3, A2);
            MUL2(A3, M[3][0], V0); FMA2(A3, M[3][1], V1, A3);
            FMA2(A3, M[3][2], V2, A3); FMA2(A3, M[3][3], V3, A3);

            // routed butterfly over b (4 lanes): lane ends with row 4a+b
            ull s0 = hi_b ? A0 : A2;
            ull s1 = hi_b ? A1 : A3;
            ull r0 = __shfl_xor_sync(FULL, s0, 2);
            ull r1 = __shfl_xor_sync(FULL, s1, 2);
            ull K0 = hi_b ? A2 : A0; ADD2(K0, K0, r0);   // row 2*hi_b
            ull K1 = hi_b ? A3 : A1; ADD2(K1, K1, r1);   // row 2*hi_b+1
            ull s2 = lo_b ? K0 : K1;
            ull r2 = __shfl_xor_sync(FULL, s2, 1);
            ull D  = lo_b ? K1 : K0; ADD2(D, D, r2);     // row 2*hi_b+lo_b = b
            float dl, dh; UNPACK2(dl, dh, D);
            const float d = dl + dh;                     // d[4a+b] = d[lane]
            u = __fdividef(u, fmaf(u, d, EPS));
        }

        // ================= Col step: c_j = M0[:,j].u, update v ==============
        {
            // gather u[4a+t], t=0..3 ; owner of u[i] is lane i
            float g0 = __shfl_sync(FULL, u, a4);
            float g1 = __shfl_sync(FULL, u, a4 + 1);
            float g2 = __shfl_sync(FULL, u, a4 + 2);
            float g3 = __shfl_sync(FULL, u, a4 + 3);
            ull U0, U1, U2, U3;
            PACK2(U0, g0, g0); PACK2(U1, g1, g1);
            PACK2(U2, g2, g2); PACK2(U3, g3, g3);

            // per-colpair partials over our 4 rows
            ull C0, C1, C2, C3;
            MUL2(C0, M[0][0], U0); FMA2(C0, M[1][0], U1, C0);
            FMA2(C0, M[2][0], U2, C0); FMA2(C0, M[3][0], U3, C0);
            MUL2(C1, M[0][1], U0); FMA2(C1, M[1][1], U1, C1);
            FMA2(C1, M[2][1], U2, C1); FMA2(C1, M[3][1], U3, C1);
            MUL2(C2, M[0][2], U0); FMA2(C2, M[1][2], U1, C2);
            FMA2(C2, M[2][2], U2, C2); FMA2(C2, M[3][2], U3, C2);
            MUL2(C3, M[0][3], U0); FMA2(C3, M[1][3], U1, C3);
            FMA2(C3, M[2][3], U2, C3); FMA2(C3, M[3][3], U3, C3);

            // routed butterfly over a (8 lanes): lane ends with col 8b+a
            ull t0 = h2 ? C0 : C2;
            ull t1 = h2 ? C1 : C3;
            ull q0 = __shfl_xor_sync(FULL, t0, 16);
            ull q1 = __shfl_xor_sync(FULL, t1, 16);
            ull L0 = h2 ? C2 : C0; ADD2(L0, L0, q0);     // colpair s = 2*h2
            ull L1 = h2 ? C3 : C1; ADD2(L1, L1, q1);     // colpair s = 2*h2+1
            ull t2 = h1 ? L0 : L1;
            ull q2 = __shfl_xor_sync(FULL, t2, 8);
            ull P  = h1 ? L1 : L0; ADD2(P, P, q2);       // colpair s = a>>1
            float pl, ph; UNPACK2(pl, ph, P);
            float t3 = h0 ? pl : ph;
            float q3 = __shfl_xor_sync(FULL, t3, 4);
            const float c = (h0 ? ph : pl) + q3;         // c[8b+a]
            v = __fdividef(v, fmaf(v, c, EPS));
        }
    }

    // ---- Epilogue: out[i][j] = u_i * M0[i][j] * v_j ----
    {
        float g0 = __shfl_sync(FULL, v, b);
        float g1 = __shfl_sync(FULL, v, b + 4);
        float g2 = __shfl_sync(FULL, v, b + 8);
        float g3 = __shfl_sync(FULL, v, b + 12);
        float g4 = __shfl_sync(FULL, v, b + 16);
        float g5 = __shfl_sync(FULL, v, b + 20);
        float g6 = __shfl_sync(FULL, v, b + 24);
        float g7 = __shfl_sync(FULL, v, b + 28);
        ull V[4];
        PACK2(V[0], g0, g1); PACK2(V[1], g2, g3);
        PACK2(V[2], g4, g5); PACK2(V[3], g6, g7);

        float e0 = __shfl_sync(FULL, u, a4);
        float e1 = __shfl_sync(FULL, u, a4 + 1);
        float e2 = __shfl_sync(FULL, u, a4 + 2);
        float e3 = __shfl_sync(FULL, u, a4 + 3);
        ull U[4];
        PACK2(U[0], e0, e0); PACK2(U[1], e1, e1);
        PACK2(U[2], e2, e2); PACK2(U[3], e3, e3);

#pragma unroll
        for (int r = 0; r < 4; r++) {
            const int rowoff = (4 * a + r) * 8 + 2 * b;
#pragma unroll
            for (int q = 0; q < 2; q++) {
                ull p0, p1;
                MUL2(p0, M[r][2 * q], V[2 * q]);
                MUL2(p0, p0, U[r]);
                MUL2(p1, M[r][2 * q + 1], V[2 * q + 1]);
                MUL2(p1, p1, U[r]);
                float4 o;
                UNPACK2(o.x, o.y, p0);
                UNPACK2(o.z, o.w, p1);
                dst[rowoff + q] = o;
            }
        }
    }
}

extern "C" void kernel_launch(void* const* d_in, const int* in_sizes, int n_in,
                              void* d_out, int out_size) {
    const float* H   = (const float*)d_in[0];
    float*       out = (float*)d_out;
    const int nmat   = in_sizes[0] / 1024;          // 32*32 per matrix
    const int blocks = (nmat + WPB - 1) / WPB;
    sinkhorn_kernel<<<blocks, WPB * 32>>>(H, out, nmat);
}